// round 2
// baseline (speedup 1.0000x reference)
#include <cuda_runtime.h>
#include <cuda_fp16.h>
#include <cstdint>

#define N_TOK 12288
#define DIM   128
#define TILE  128
#define NTILE 96          // N_TOK / TILE
#define PSTR  136         // half-element stride of P/V smem rows (272 B: conflict-free ldmatrix)
#define PSCALE 0.7f       // keeps p in [0.5,1) fp16 binade; cancels in p/sum(p)

// smem byte offsets
#define SM_P   0
#define SM_V   34816
#define SM_WH1 69632
#define SM_RS  70144
#define SM_N2  70656
#define SM_N2P 71168
#define SMEM_TOTAL 73216

// ---------------- scratch (static device globals; no runtime allocation) ----------------
__device__ __half g_xt[(size_t)N_TOK * DIM];   // x_tan in fp16, row-major [N, D]
__device__ float  g_wh1[N_TOK];
__device__ float  g_wh2[N_TOK];

// ---------------- small PTX helpers ----------------
__device__ __forceinline__ uint32_t smem_u32(const void* p) {
    return (uint32_t)__cvta_generic_to_shared(p);
}
__device__ __forceinline__ void ldsm_x4(uint32_t addr, uint32_t& r0, uint32_t& r1,
                                        uint32_t& r2, uint32_t& r3) {
    asm volatile("ldmatrix.sync.aligned.m8n8.x4.shared.b16 {%0,%1,%2,%3}, [%4];"
                 : "=r"(r0), "=r"(r1), "=r"(r2), "=r"(r3) : "r"(addr));
}
__device__ __forceinline__ void ldsm_x4_t(uint32_t addr, uint32_t& r0, uint32_t& r1,
                                          uint32_t& r2, uint32_t& r3) {
    asm volatile("ldmatrix.sync.aligned.m8n8.x4.trans.shared.b16 {%0,%1,%2,%3}, [%4];"
                 : "=r"(r0), "=r"(r1), "=r"(r2), "=r"(r3) : "r"(addr));
}
__device__ __forceinline__ void mma16816(float* c, const uint32_t* a, const uint32_t* b) {
    asm volatile("mma.sync.aligned.m16n8k16.row.col.f32.f16.f16.f32 "
                 "{%0,%1,%2,%3}, {%4,%5,%6,%7}, {%8,%9}, {%0,%1,%2,%3};"
                 : "+f"(c[0]), "+f"(c[1]), "+f"(c[2]), "+f"(c[3])
                 : "r"(a[0]), "r"(a[1]), "r"(a[2]), "r"(a[3]), "r"(b[0]), "r"(b[1]));
}

// ---------------- prep: logmap0 + wh1/wh2 + fp16 x_tan ----------------
// one warp per row; lane covers 4 consecutive dims
__global__ __launch_bounds__(256) void prep_kernel(const float* __restrict__ x,
                                                   const float* __restrict__ a) {
    int gw   = (blockIdx.x * blockDim.x + threadIdx.x) >> 5;
    int lane = threadIdx.x & 31;
    if (gw >= N_TOK) return;

    const float4 xv = ((const float4*)(x + (size_t)gw * DIM))[lane];
    float ss = xv.x * xv.x + xv.y * xv.y + xv.z * xv.z + xv.w * xv.w;
    #pragma unroll
    for (int o = 16; o; o >>= 1) ss += __shfl_xor_sync(0xffffffffu, ss, o);

    float norm = sqrtf(ss);
    float n    = fminf(fmaxf(norm, 1e-7f), 1.0f - 1e-7f);
    float fac  = atanhf(n) / n;               // logmap0 factor (clipped norm in both places)

    float t0 = xv.x * fac, t1 = xv.y * fac, t2 = xv.z * fac, t3 = xv.w * fac;

    const float4 a1 = ((const float4*)a)[lane];
    const float4 a2 = ((const float4*)(a + DIM))[lane];
    float w1 = t0 * a1.x + t1 * a1.y + t2 * a1.z + t3 * a1.w;
    float w2 = t0 * a2.x + t1 * a2.y + t2 * a2.z + t3 * a2.w;
    #pragma unroll
    for (int o = 16; o; o >>= 1) {
        w1 += __shfl_xor_sync(0xffffffffu, w1, o);
        w2 += __shfl_xor_sync(0xffffffffu, w2, o);
    }

    __half2* dst = (__half2*)(g_xt + (size_t)gw * DIM);
    dst[lane * 2]     = __floats2half2_rn(t0, t1);
    dst[lane * 2 + 1] = __floats2half2_rn(t2, t3);

    if (lane == 0) { g_wh1[gw] = w1; g_wh2[gw] = w2; }
}

// ---------------- fused attention: P-gen + HMMA + expmap/proj epilogue ----------------
__global__ __launch_bounds__(512) void attn_kernel(const int* __restrict__ adj,
                                                   float* __restrict__ out) {
    extern __shared__ char smem[];
    __half* Pm   = (__half*)(smem + SM_P);
    __half* Vm   = (__half*)(smem + SM_V);
    float*  wh1s = (float*)(smem + SM_WH1);
    float*  rs   = (float*)(smem + SM_RS);
    float*  fac  = (float*)(smem + SM_N2);
    float*  n2p  = (float*)(smem + SM_N2P);

    const int tid = threadIdx.x;
    const int i0  = blockIdx.x * TILE;

    if (tid < TILE) { wh1s[tid] = g_wh1[i0 + tid]; rs[tid] = 0.f; }
    __syncthreads();

    // P-gen mapping: thread -> (row il, 32-wide j chunk jq)
    const int il = tid >> 2, jq = tid & 3;
    const int lane = tid & 31, wid = tid >> 5;
    const int wm = wid & 3, wn = wid >> 2;   // warp tile: rows wm*32+..., cols wn*32+...

    float acc[2][4][4];
    #pragma unroll
    for (int mt = 0; mt < 2; ++mt)
        #pragma unroll
        for (int nt = 0; nt < 4; ++nt)
            #pragma unroll
            for (int e = 0; e < 4; ++e) acc[mt][nt][e] = 0.f;

    const float w1 = wh1s[il];
    const int4* arowb = (const int4*)(adj + (size_t)(i0 + il) * N_TOK);
    const uint32_t pbase = smem_u32(Pm);
    const uint32_t vbase = smem_u32(Vm);

    #pragma unroll 1
    for (int jt = 0; jt < NTILE; ++jt) {
        const int j0 = jt * TILE;
        __syncthreads();   // previous MMA done reading P/V

        // ---- V tile copy (fp16 x_tan rows j0..j0+127, L2-resident) ----
        {
            const uint4* vs = (const uint4*)(g_xt + (size_t)j0 * DIM);
            #pragma unroll
            for (int q = 0; q < 4; ++q) {
                int idx = q * 512 + tid;
                int r = idx >> 4, cc = idx & 15;
                *(uint4*)(Vm + r * PSTR + cc * 8) = vs[idx];
            }
        }

        // ---- P tile: masked exp, fp16, + fp32 rowsum ----
        {
            const float4* w2p = (const float4*)(g_wh2 + j0) + jq * 8;
            union { __half h[32]; uint4 u[4]; } pk;
            float psum = 0.f;
            #pragma unroll
            for (int c = 0; c < 8; ++c) {
                int4   av = arowb[(j0 >> 2) + jq * 8 + c];
                float4 w2 = w2p[c];
                float s0 = w1 + w2.x, s1 = w1 + w2.y, s2 = w1 + w2.z, s3 = w1 + w2.w;
                s0 = fmaxf(s0, 0.2f * s0); s1 = fmaxf(s1, 0.2f * s1);
                s2 = fmaxf(s2, 0.2f * s2); s3 = fmaxf(s3, 0.2f * s3);
                float p0 = av.x ? PSCALE * __expf(s0) : 0.f;
                float p1 = av.y ? PSCALE * __expf(s1) : 0.f;
                float p2 = av.z ? PSCALE * __expf(s2) : 0.f;
                float p3 = av.w ? PSCALE * __expf(s3) : 0.f;
                psum += (p0 + p1) + (p2 + p3);
                pk.h[c * 4 + 0] = __float2half_rn(p0);
                pk.h[c * 4 + 1] = __float2half_rn(p1);
                pk.h[c * 4 + 2] = __float2half_rn(p2);
                pk.h[c * 4 + 3] = __float2half_rn(p3);
            }
            uint4* pd = (uint4*)(Pm + il * PSTR + jq * 32);
            #pragma unroll
            for (int q = 0; q < 4; ++q) pd[q] = pk.u[q];

            psum += __shfl_xor_sync(0xffffffffu, psum, 1);
            psum += __shfl_xor_sync(0xffffffffu, psum, 2);
            if ((tid & 3) == 0) rs[il] += psum;   // unique writer per row
        }

        __syncthreads();   // P/V visible

        // ---- MMA: C[128x128] += P[128x128] * V[128x128] ----
        #pragma unroll
        for (int k = 0; k < 8; ++k) {
            uint32_t afr[2][4], bfr[4][2];
            uint32_t aaddr = pbase + (uint32_t)(((wm * 32 + (lane & 15)) * PSTR
                                     + k * 16 + (lane >> 4) * 8) * 2);
            ldsm_x4(aaddr,                afr[0][0], afr[0][1], afr[0][2], afr[0][3]);
            ldsm_x4(aaddr + 16 * PSTR * 2, afr[1][0], afr[1][1], afr[1][2], afr[1][3]);

            uint32_t baddr = vbase + (uint32_t)(((k * 16 + (lane & 15)) * PSTR
                                     + wn * 32 + (lane >> 4) * 8) * 2);
            ldsm_x4_t(baddr,      bfr[0][0], bfr[0][1], bfr[1][0], bfr[1][1]);
            ldsm_x4_t(baddr + 32, bfr[2][0], bfr[2][1], bfr[3][0], bfr[3][1]);

            #pragma unroll
            for (int mt = 0; mt < 2; ++mt)
                #pragma unroll
                for (int nt = 0; nt < 4; ++nt)
                    mma16816(acc[mt][nt], afr[mt], bfr[nt]);
        }
    }

    // ---------------- epilogue: /rowsum, row norm, expmap0 + proj ----------------
    #pragma unroll
    for (int mt = 0; mt < 2; ++mt) {
        int rlo = wm * 32 + mt * 16 + (lane >> 2);
        int rhi = rlo + 8;
        float invlo = 1.f / rs[rlo];
        float invhi = 1.f / rs[rhi];
        float slo = 0.f, shi = 0.f;
        #pragma unroll
        for (int nt = 0; nt < 4; ++nt) {
            acc[mt][nt][0] *= invlo; acc[mt][nt][1] *= invlo;
            acc[mt][nt][2] *= invhi; acc[mt][nt][3] *= invhi;
            slo += acc[mt][nt][0] * acc[mt][nt][0] + acc[mt][nt][1] * acc[mt][nt][1];
            shi += acc[mt][nt][2] * acc[mt][nt][2] + acc[mt][nt][3] * acc[mt][nt][3];
        }
        slo += __shfl_xor_sync(0xffffffffu, slo, 1);
        slo += __shfl_xor_sync(0xffffffffu, slo, 2);
        shi += __shfl_xor_sync(0xffffffffu, shi, 1);
        shi += __shfl_xor_sync(0xffffffffu, shi, 2);
        if ((lane & 3) == 0) {          // unique (wn,row) writer -> deterministic
            n2p[wn * 128 + rlo] = slo;
            n2p[wn * 128 + rhi] = shi;
        }
    }
    __syncthreads();
    if (tid < 128) {
        float s  = n2p[tid] + n2p[128 + tid] + n2p[256 + tid] + n2p[384 + tid];
        float nn = fmaxf(sqrtf(s), 1e-7f);      // expmap0 norm clip (lower only)
        float t  = tanhf(nn);
        fac[tid] = (t > 0.999f) ? (0.999f / nn) : (t / nn);   // fused expmap0 + proj
    }
    __syncthreads();
    #pragma unroll
    for (int mt = 0; mt < 2; ++mt) {
        int rlo = wm * 32 + mt * 16 + (lane >> 2);
        int rhi = rlo + 8;
        float flo = fac[rlo], fhi = fac[rhi];
        #pragma unroll
        for (int nt = 0; nt < 4; ++nt) {
            int col = wn * 32 + nt * 8 + 2 * (lane & 3);
            float2 olo = make_float2(acc[mt][nt][0] * flo, acc[mt][nt][1] * flo);
            float2 ohi = make_float2(acc[mt][nt][2] * fhi, acc[mt][nt][3] * fhi);
            *(float2*)(out + (size_t)(i0 + rlo) * DIM + col) = olo;
            *(float2*)(out + (size_t)(i0 + rhi) * DIM + col) = ohi;
        }
    }
}

// ---------------- launch ----------------
extern "C" void kernel_launch(void* const* d_in, const int* in_sizes, int n_in,
                              void* d_out, int out_size) {
    const float* x   = (const float*)d_in[0];
    const int*   adj = (const int*)d_in[1];
    const float* a   = (const float*)d_in[2];
    float*       out = (float*)d_out;

    cudaFuncSetAttribute(attn_kernel, cudaFuncAttributeMaxDynamicSharedMemorySize, SMEM_TOTAL);

    prep_kernel<<<N_TOK / 8, 256>>>(x, a);
    attn_kernel<<<NTILE, 512, SMEM_TOTAL>>>(adj, out);
}

// round 3
// speedup vs baseline: 1.6800x; 1.6800x over previous
#include <cuda_runtime.h>
#include <cuda_fp16.h>
#include <cstdint>

#define N_TOK 12288
#define DIM   128
#define TILE  128
#define NTILE 96          // N_TOK / TILE
#define NWRD  384         // mask words per row (N_TOK/32)
#define PSTR  136         // half-element stride of P/V smem rows (272 B)
#define PSCALE 0.7f       // keeps p in ~[0.5,2) fp16 binades; cancels in p/sum(p)
#define PVB   34816       // bytes per P/V tile buffer (128 * 136 * 2)

// smem byte offsets
#define SM_P    0          // 2 buffers
#define SM_V    69632      // 3 buffers
#define SM_E2   174080     // 2 x 160 floats (40-float sections per jq: bank-spread)
#define SM_E2P  175360
#define SM_E1   176640     // 128 floats
#define SM_E1P  177152
#define SM_RS   177664
#define SM_N2P  178176     // 512 floats
#define SM_FAC  180224     // 128 floats
#define SMEM_TOTAL 180736

// ---------------- scratch (static device globals; no runtime allocation) ----------------
__device__ __half    g_xt[(size_t)N_TOK * DIM];       // x_tan fp16 [N, D]
__device__ uint32_t  g_mask[(size_t)N_TOK * NWRD];    // packed adj bits, 18.9 MB
__device__ float     g_e1[N_TOK];    // 0.7*exp(wh1)
__device__ float     g_e1p[N_TOK];   // 0.7*exp(0.2*wh1)
__device__ float     g_e2[N_TOK];    // exp(wh2)
__device__ float     g_e2p[N_TOK];   // exp(0.2*wh2)

// ---------------- PTX helpers ----------------
__device__ __forceinline__ uint32_t smem_u32(const void* p) {
    return (uint32_t)__cvta_generic_to_shared(p);
}
__device__ __forceinline__ void ldsm_x4(uint32_t addr, uint32_t& r0, uint32_t& r1,
                                        uint32_t& r2, uint32_t& r3) {
    asm volatile("ldmatrix.sync.aligned.m8n8.x4.shared.b16 {%0,%1,%2,%3}, [%4];"
                 : "=r"(r0), "=r"(r1), "=r"(r2), "=r"(r3) : "r"(addr));
}
__device__ __forceinline__ void ldsm_x4_t(uint32_t addr, uint32_t& r0, uint32_t& r1,
                                          uint32_t& r2, uint32_t& r3) {
    asm volatile("ldmatrix.sync.aligned.m8n8.x4.trans.shared.b16 {%0,%1,%2,%3}, [%4];"
                 : "=r"(r0), "=r"(r1), "=r"(r2), "=r"(r3) : "r"(addr));
}
__device__ __forceinline__ void mma16816(float* c, const uint32_t* a, const uint32_t* b) {
    asm volatile("mma.sync.aligned.m16n8k16.row.col.f32.f16.f16.f32 "
                 "{%0,%1,%2,%3}, {%4,%5,%6,%7}, {%8,%9}, {%0,%1,%2,%3};"
                 : "+f"(c[0]), "+f"(c[1]), "+f"(c[2]), "+f"(c[3])
                 : "r"(a[0]), "r"(a[1]), "r"(a[2]), "r"(a[3]), "r"(b[0]), "r"(b[1]));
}

// ---------------- pack: adj int32 -> bitmask (pure DRAM stream) ----------------
__global__ __launch_bounds__(256) void pack_kernel(const int* __restrict__ adj) {
    const int64_t nwords = (int64_t)N_TOK * NWRD;          // 4,718,592 (mult of 4)
    const int lane = threadIdx.x & 31;
    int64_t warp  = (int64_t)(blockIdx.x * (blockDim.x >> 5)) + (threadIdx.x >> 5);
    int64_t stride = (int64_t)gridDim.x * (blockDim.x >> 5) * 4;

    for (int64_t w = warp * 4; w < nwords; w += stride) {
        int v0 = adj[(w + 0) * 32 + lane];
        int v1 = adj[(w + 1) * 32 + lane];
        int v2 = adj[(w + 2) * 32 + lane];
        int v3 = adj[(w + 3) * 32 + lane];
        uint32_t m0 = __ballot_sync(0xffffffffu, v0);
        uint32_t m1 = __ballot_sync(0xffffffffu, v1);
        uint32_t m2 = __ballot_sync(0xffffffffu, v2);
        uint32_t m3 = __ballot_sync(0xffffffffu, v3);
        if (lane == 0)
            *(uint4*)(g_mask + w) = make_uint4(m0, m1, m2, m3);
    }
}

// ---------------- prep: logmap0 + wh1/wh2 + exp factors + fp16 x_tan ----------------
__global__ __launch_bounds__(256) void prep_kernel(const float* __restrict__ x,
                                                   const float* __restrict__ a) {
    int gw   = (blockIdx.x * blockDim.x + threadIdx.x) >> 5;
    int lane = threadIdx.x & 31;
    if (gw >= N_TOK) return;

    const float4 xv = ((const float4*)(x + (size_t)gw * DIM))[lane];
    float ss = xv.x * xv.x + xv.y * xv.y + xv.z * xv.z + xv.w * xv.w;
    #pragma unroll
    for (int o = 16; o; o >>= 1) ss += __shfl_xor_sync(0xffffffffu, ss, o);

    float norm = sqrtf(ss);
    float n    = fminf(fmaxf(norm, 1e-7f), 1.0f - 1e-7f);
    float fac  = atanhf(n) / n;

    float t0 = xv.x * fac, t1 = xv.y * fac, t2 = xv.z * fac, t3 = xv.w * fac;

    const float4 a1 = ((const float4*)a)[lane];
    const float4 a2 = ((const float4*)(a + DIM))[lane];
    float w1 = t0 * a1.x + t1 * a1.y + t2 * a1.z + t3 * a1.w;
    float w2 = t0 * a2.x + t1 * a2.y + t2 * a2.z + t3 * a2.w;
    #pragma unroll
    for (int o = 16; o; o >>= 1) {
        w1 += __shfl_xor_sync(0xffffffffu, w1, o);
        w2 += __shfl_xor_sync(0xffffffffu, w2, o);
    }

    __half2* dst = (__half2*)(g_xt + (size_t)gw * DIM);
    dst[lane * 2]     = __floats2half2_rn(t0, t1);
    dst[lane * 2 + 1] = __floats2half2_rn(t2, t3);

    if (lane == 0) {
        g_e1 [gw] = PSCALE * __expf(w1);
        g_e1p[gw] = PSCALE * __expf(0.2f * w1);
        g_e2 [gw] = __expf(w2);
        g_e2p[gw] = __expf(0.2f * w2);
    }
}

// ---------------- fused attention ----------------
__global__ __launch_bounds__(512) void attn_kernel(float* __restrict__ out) {
    extern __shared__ char smem[];
    float* E2b  = (float*)(smem + SM_E2);    // [2][160] (sections of 40 per jq)
    float* E2Pb = (float*)(smem + SM_E2P);
    float* E1s  = (float*)(smem + SM_E1);
    float* E1Ps = (float*)(smem + SM_E1P);
    float* rs   = (float*)(smem + SM_RS);
    float* n2p  = (float*)(smem + SM_N2P);
    float* fac  = (float*)(smem + SM_FAC);

    const int tid = threadIdx.x;
    const int i0  = blockIdx.x * TILE;

    if (tid < TILE) {
        E1s[tid]  = g_e1[i0 + tid];
        E1Ps[tid] = g_e1p[i0 + tid];
        rs[tid]   = 0.f;
    }

    const int il = tid >> 2, jq = tid & 3;
    const int lane = tid & 31, wid = tid >> 5;
    const int wm = wid & 3, wn = wid >> 2;

    float acc[2][4][4];
    #pragma unroll
    for (int mt = 0; mt < 2; ++mt)
        #pragma unroll
        for (int nt = 0; nt < 4; ++nt)
            #pragma unroll
            for (int e = 0; e < 4; ++e) acc[mt][nt][e] = 0.f;

    const uint32_t pbase = smem_u32(smem + SM_P);
    const uint32_t vbase = smem_u32(smem + SM_V);
    const uint32_t* mrow = g_mask + (size_t)(i0 + il) * NWRD;

    // ---- prologue: stage tile 0 (V buffer 0, E2 buffer 0, mask reg) ----
    {
        const uint4* vs = (const uint4*)g_xt;   // tile 0 rows
        __half* Vm = (__half*)(smem + SM_V);    // buffer 0
        #pragma unroll
        for (int q = 0; q < 4; ++q) {
            int idx = q * 512 + tid;
            int r = idx >> 4, cc = idx & 15;
            *(uint4*)(Vm + r * PSTR + cc * 8) = vs[idx];
        }
        if (tid < 32)
            *(float4*)(E2b + (tid >> 3) * 40 + (tid & 7) * 4) = *(const float4*)(g_e2 + tid * 4);
        else if (tid < 64) {
            int k = tid - 32;
            *(float4*)(E2Pb + (k >> 3) * 40 + (k & 7) * 4) = *(const float4*)(g_e2p + k * 4);
        }
    }
    uint32_t m_cur = mrow[jq];

    #pragma unroll 1
    for (int jt = 0; jt < NTILE; ++jt) {
        const int pcur = jt & 1;
        const int vprev = (jt + 2) % 3;      // (jt-1)%3
        const int vnext = (jt + 1) % 3;
        uint32_t m_next = 0;

        __syncthreads();

        // ---- prefetch tile jt+1: V, E2/E2P, mask ----
        if (jt + 1 < NTILE) {
            const int j1 = (jt + 1) * TILE;
            const uint4* vs = (const uint4*)(g_xt + (size_t)j1 * DIM);
            __half* Vm = (__half*)(smem + SM_V + vnext * PVB);
            #pragma unroll
            for (int q = 0; q < 4; ++q) {
                int idx = q * 512 + tid;
                int r = idx >> 4, cc = idx & 15;
                *(uint4*)(Vm + r * PSTR + cc * 8) = vs[idx];
            }
            const int eb = (jt + 1) & 1;
            if (tid < 32)
                *(float4*)(E2b + eb * 160 + (tid >> 3) * 40 + (tid & 7) * 4)
                    = *(const float4*)(g_e2 + j1 + tid * 4);
            else if (tid < 64) {
                int k = tid - 32;
                *(float4*)(E2Pb + eb * 160 + (k >> 3) * 40 + (k & 7) * 4)
                    = *(const float4*)(g_e2p + j1 + k * 4);
            }
            m_next = mrow[(jt + 1) * 4 + jq];
        }

        // ---- P-gen tile jt (no MUFU: p = mask * max(E1*E2, E1p*E2p)) ----
        {
            const float e1  = E1s[il];
            const float e1p = E1Ps[il];
            const float4* e2v  = (const float4*)(E2b  + pcur * 160 + jq * 40);
            const float4* e2pv = (const float4*)(E2Pb + pcur * 160 + jq * 40);
            __half* Pm = (__half*)(smem + SM_P + pcur * PVB);
            union { __half h[32]; uint4 u[4]; } pk;
            float psum = 0.f;
            #pragma unroll
            for (int c = 0; c < 8; ++c) {
                float4 ev  = e2v[c];
                float4 epv = e2pv[c];
                float p0 = fmaxf(e1 * ev.x, e1p * epv.x);
                float p1 = fmaxf(e1 * ev.y, e1p * epv.y);
                float p2 = fmaxf(e1 * ev.z, e1p * epv.z);
                float p3 = fmaxf(e1 * ev.w, e1p * epv.w);
                p0 = (m_cur >> (c * 4 + 0)) & 1u ? p0 : 0.f;
                p1 = (m_cur >> (c * 4 + 1)) & 1u ? p1 : 0.f;
                p2 = (m_cur >> (c * 4 + 2)) & 1u ? p2 : 0.f;
                p3 = (m_cur >> (c * 4 + 3)) & 1u ? p3 : 0.f;
                psum += (p0 + p1) + (p2 + p3);
                pk.h[c * 4 + 0] = __float2half_rn(p0);
                pk.h[c * 4 + 1] = __float2half_rn(p1);
                pk.h[c * 4 + 2] = __float2half_rn(p2);
                pk.h[c * 4 + 3] = __float2half_rn(p3);
            }
            uint4* pd = (uint4*)(Pm + il * PSTR + jq * 32);
            #pragma unroll
            for (int q = 0; q < 4; ++q) pd[q] = pk.u[q];

            psum += __shfl_xor_sync(0xffffffffu, psum, 1);
            psum += __shfl_xor_sync(0xffffffffu, psum, 2);
            if (jq == 0) rs[il] += psum;
        }

        // ---- MMA tile jt-1 (overlaps with other warps' P-gen) ----
        if (jt) {
            const uint32_t pb = pbase + ((jt - 1) & 1) * PVB;
            const uint32_t vb = vbase + vprev * PVB;
            #pragma unroll
            for (int k = 0; k < 8; ++k) {
                uint32_t afr[2][4], bfr[4][2];
                uint32_t aaddr = pb + (uint32_t)(((wm * 32 + (lane & 15)) * PSTR
                                         + k * 16 + (lane >> 4) * 8) * 2);
                ldsm_x4(aaddr,                 afr[0][0], afr[0][1], afr[0][2], afr[0][3]);
                ldsm_x4(aaddr + 16 * PSTR * 2, afr[1][0], afr[1][1], afr[1][2], afr[1][3]);

                uint32_t baddr = vb + (uint32_t)(((k * 16 + (lane & 15)) * PSTR
                                         + wn * 32 + (lane >> 4) * 8) * 2);
                ldsm_x4_t(baddr,      bfr[0][0], bfr[0][1], bfr[1][0], bfr[1][1]);
                ldsm_x4_t(baddr + 32, bfr[2][0], bfr[2][1], bfr[3][0], bfr[3][1]);

                #pragma unroll
                for (int mt = 0; mt < 2; ++mt)
                    #pragma unroll
                    for (int nt = 0; nt < 4; ++nt)
                        mma16816(acc[mt][nt], afr[mt], bfr[nt]);
            }
        }
        m_cur = m_next;
    }

    // ---- drain: MMA for tile 95 ----
    __syncthreads();
    {
        const uint32_t pb = pbase + ((NTILE - 1) & 1) * PVB;
        const uint32_t vb = vbase + ((NTILE - 1) % 3) * PVB;
        #pragma unroll
        for (int k = 0; k < 8; ++k) {
            uint32_t afr[2][4], bfr[4][2];
            uint32_t aaddr = pb + (uint32_t)(((wm * 32 + (lane & 15)) * PSTR
                                     + k * 16 + (lane >> 4) * 8) * 2);
            ldsm_x4(aaddr,                 afr[0][0], afr[0][1], afr[0][2], afr[0][3]);
            ldsm_x4(aaddr + 16 * PSTR * 2, afr[1][0], afr[1][1], afr[1][2], afr[1][3]);

            uint32_t baddr = vb + (uint32_t)(((k * 16 + (lane & 15)) * PSTR
                                     + wn * 32 + (lane >> 4) * 8) * 2);
            ldsm_x4_t(baddr,      bfr[0][0], bfr[0][1], bfr[1][0], bfr[1][1]);
            ldsm_x4_t(baddr + 32, bfr[2][0], bfr[2][1], bfr[3][0], bfr[3][1]);

            #pragma unroll
            for (int mt = 0; mt < 2; ++mt)
                #pragma unroll
                for (int nt = 0; nt < 4; ++nt)
                    mma16816(acc[mt][nt], afr[mt], bfr[nt]);
        }
    }

    // ---------------- epilogue: /rowsum, row norm, expmap0 + proj ----------------
    #pragma unroll
    for (int mt = 0; mt < 2; ++mt) {
        int rlo = wm * 32 + mt * 16 + (lane >> 2);
        int rhi = rlo + 8;
        float invlo = 1.f / rs[rlo];
        float invhi = 1.f / rs[rhi];
        float slo = 0.f, shi = 0.f;
        #pragma unroll
        for (int nt = 0; nt < 4; ++nt) {
            acc[mt][nt][0] *= invlo; acc[mt][nt][1] *= invlo;
            acc[mt][nt][2] *= invhi; acc[mt][nt][3] *= invhi;
            slo += acc[mt][nt][0] * acc[mt][nt][0] + acc[mt][nt][1] * acc[mt][nt][1];
            shi += acc[mt][nt][2] * acc[mt][nt][2] + acc[mt][nt][3] * acc[mt][nt][3];
        }
        slo += __shfl_xor_sync(0xffffffffu, slo, 1);
        slo += __shfl_xor_sync(0xffffffffu, slo, 2);
        shi += __shfl_xor_sync(0xffffffffu, shi, 1);
        shi += __shfl_xor_sync(0xffffffffu, shi, 2);
        if ((lane & 3) == 0) {
            n2p[wn * 128 + rlo] = slo;
            n2p[wn * 128 + rhi] = shi;
        }
    }
    __syncthreads();
    if (tid < 128) {
        float s  = n2p[tid] + n2p[128 + tid] + n2p[256 + tid] + n2p[384 + tid];
        float nn = fmaxf(sqrtf(s), 1e-7f);
        float t  = tanhf(nn);
        fac[tid] = (t > 0.999f) ? (0.999f / nn) : (t / nn);
    }
    __syncthreads();
    #pragma unroll
    for (int mt = 0; mt < 2; ++mt) {
        int rlo = wm * 32 + mt * 16 + (lane >> 2);
        int rhi = rlo + 8;
        float flo = fac[rlo], fhi = fac[rhi];
        #pragma unroll
        for (int nt = 0; nt < 4; ++nt) {
            int col = wn * 32 + nt * 8 + 2 * (lane & 3);
            float2 olo = make_float2(acc[mt][nt][0] * flo, acc[mt][nt][1] * flo);
            float2 ohi = make_float2(acc[mt][nt][2] * fhi, acc[mt][nt][3] * fhi);
            *(float2*)(out + (size_t)(i0 + rlo) * DIM + col) = olo;
            *(float2*)(out + (size_t)(i0 + rhi) * DIM + col) = ohi;
        }
    }
}

// ---------------- launch ----------------
extern "C" void kernel_launch(void* const* d_in, const int* in_sizes, int n_in,
                              void* d_out, int out_size) {
    const float* x   = (const float*)d_in[0];
    const int*   adj = (const int*)d_in[1];
    const float* a   = (const float*)d_in[2];
    float*       out = (float*)d_out;

    cudaFuncSetAttribute(attn_kernel, cudaFuncAttributeMaxDynamicSharedMemorySize, SMEM_TOTAL);

    prep_kernel<<<N_TOK / 8, 256>>>(x, a);
    pack_kernel<<<1184, 256>>>(adj);
    attn_kernel<<<NTILE, 512, SMEM_TOTAL>>>(out);
}